// round 14
// baseline (speedup 1.0000x reference)
#include <cuda_runtime.h>
#include <cuda_fp16.h>
#include <math.h>
#include <stdint.h>

#define H 1024
#define V 32000
#define L 4096
#define NC 16            // K chunks of 64 fp16 over K=1024

// ---------------- device scratch ----------------
__device__ __half g_ench[(size_t)L * 1024];   // enc fp16, 8 MB
__device__ __half g_uWh[(size_t)H * 1024];    // uW fp16, 2 MB
__device__ __half g_outWh[(size_t)V * 1024];  // outW fp16, 64 MB (converted inside k2 MMA blocks)
__device__ float g_cpart[64 * H];
__device__ float g_scores[L];
__device__ float g_q[H];
__device__ float g_attn[L];
__device__ float g_context[H];
__device__ float g_x[H];
__device__ float g_xemb[H];      // cW_emb @ embedded + cb (prologue)
__device__ float g_gi[3 * H];
__device__ float g_gh[3 * H];
__device__ float g_ov[H];
__device__ unsigned g_k2cnt;
__device__ unsigned g_bar_cnt;
__device__ volatile unsigned g_bar_gen;

// ---------------- helpers ----------------
__device__ __forceinline__ uint32_t smem_u32(const void* p) {
    uint32_t a;
    asm("{ .reg .u64 t; cvta.to.shared.u64 t, %1; cvt.u32.u64 %0, t; }" : "=r"(a) : "l"(p));
    return a;
}
__device__ __forceinline__ uint32_t sw(uint32_t off) {   // Swizzle<3,4,3> on 128B rows
    return off ^ ((off >> 3) & 0x70u);
}
#define CP_ASYNC16(dst, src) \
    asm volatile("cp.async.cg.shared.global [%0], [%1], 16;" :: "r"(dst), "l"(src) : "memory")
#define CP_COMMIT() asm volatile("cp.async.commit_group;" ::: "memory")
#define CP_WAIT(n)  asm volatile("cp.async.wait_group %0;" :: "n"(n) : "memory")
#define LDSM_X4(r, a) \
    asm volatile("ldmatrix.sync.aligned.m8n8.x4.shared.b16 {%0,%1,%2,%3}, [%4];" \
                 : "=r"((r)[0]), "=r"((r)[1]), "=r"((r)[2]), "=r"((r)[3]) : "r"(a))

__device__ __forceinline__ void mma_f16(float* c, const uint32_t* a, uint32_t b0, uint32_t b1) {
    asm volatile("mma.sync.aligned.m16n8k16.row.col.f32.f16.f16.f32 "
                 "{%0,%1,%2,%3}, {%4,%5,%6,%7}, {%8,%9}, {%0,%1,%2,%3};"
                 : "+f"(c[0]), "+f"(c[1]), "+f"(c[2]), "+f"(c[3])
                 : "r"(a[0]), "r"(a[1]), "r"(a[2]), "r"(a[3]), "r"(b0), "r"(b1));
}

__device__ __forceinline__ float warp_sum(float v) {
#pragma unroll
    for (int o = 16; o; o >>= 1) v += __shfl_xor_sync(0xffffffffu, v, o);
    return v;
}
__device__ __forceinline__ float warp_max(float v) {
#pragma unroll
    for (int o = 16; o; o >>= 1) v = fmaxf(v, __shfl_xor_sync(0xffffffffu, v, o));
    return v;
}
__device__ __forceinline__ uint32_t pkh(__half a, __half b) {
    uint16_t ua = *(uint16_t*)&a, ub = *(uint16_t*)&b;
    return (uint32_t)ua | ((uint32_t)ub << 16);
}

// grid-wide barrier for 128 co-resident blocks
__device__ __forceinline__ void grid_sync_128(unsigned target) {
    __threadfence();
    __syncthreads();
    if (threadIdx.x == 0) {
        unsigned v = atomicAdd(&g_bar_cnt, 1u);
        if (v == 127u) {
            g_bar_cnt = 0u;
            __threadfence();
            g_bar_gen = target;
        } else {
            while ((int)(g_bar_gen - target) < 0) {}
            __threadfence();
        }
    }
    __syncthreads();
}

// ---------------- fused prologue ----------------
#define PRO_BLOCKS (L + H + 128 + 384 + 128)

__global__ void __launch_bounds__(256) k_prologue(const float* __restrict__ enc,
                                                  const float* __restrict__ uW,
                                                  const float* __restrict__ h0,
                                                  const float* __restrict__ wW,
                                                  const float* __restrict__ wb,
                                                  const float* __restrict__ ub,
                                                  const float* __restrict__ w_hh,
                                                  const float* __restrict__ b_hh,
                                                  const float* __restrict__ cW,
                                                  const float* __restrict__ cb,
                                                  const float* __restrict__ emb,
                                                  const int* __restrict__ tok) {
    int b = blockIdx.x;
    int tid = threadIdx.x;
    if (b < L + H) {
        bool isA = (b < L);
        int r = isA ? b : b - L;
        if (isA && tid == 0) g_scores[r] = 0.f;
        const float4* src = (const float4*)((isA ? enc : uW) + (size_t)r * H);
        float4 v = src[tid];
        uint2 w = make_uint2(pkh(__float2half_rn(v.x), __float2half_rn(v.y)),
                             pkh(__float2half_rn(v.z), __float2half_rn(v.w)));
        __half* dst = (isA ? g_ench : g_uWh) + (size_t)r * 1024;
        ((uint2*)dst)[tid] = w;
    } else if (b < L + H + 128) {
        int warp = ((b - L - H) << 3) + (tid >> 5);
        int lane = tid & 31;
        const float4* row = (const float4*)(wW + (size_t)warp * H);
        const float4* h4 = (const float4*)h0;
        float s = 0.f;
#pragma unroll
        for (int i = 0; i < 8; i++) {
            float4 a = row[lane + 32 * i];
            float4 hh = h4[lane + 32 * i];
            s += a.x * hh.x + a.y * hh.y + a.z * hh.z + a.w * hh.w;
        }
        s = warp_sum(s);
        if (lane == 0) g_q[warp] = s + wb[warp] + ub[warp];
    } else if (b < L + H + 512) {
        int idx = ((b - L - H - 128) << 3) + (tid >> 5);   // 0..3071
        int lane = tid & 31;
        const float4* row = (const float4*)(w_hh + (size_t)idx * H);
        const float4* h4 = (const float4*)h0;
        float s = 0.f;
#pragma unroll
        for (int i = 0; i < 8; i++) {
            float4 a = row[lane + 32 * i];
            float4 hh = h4[lane + 32 * i];
            s += a.x * hh.x + a.y * hh.y + a.z * hh.z + a.w * hh.w;
        }
        s = warp_sum(s);
        if (lane == 0) g_gh[idx] = s + b_hh[idx];
    } else {
        int row = ((b - L - H - 512) << 3) + (tid >> 5);   // 0..1023
        int lane = tid & 31;
        const float4* wr = (const float4*)(cW + (size_t)row * 2 * H + H);
        const float4* e4 = (const float4*)(emb + (size_t)tok[0] * H);
        float s = 0.f;
#pragma unroll
        for (int i = 0; i < 8; i++) {
            float4 a = wr[lane + 32 * i];
            float4 e = e4[lane + 32 * i];
            s += a.x * e.x + a.y * e.y + a.z * e.z + a.w * e.w;
        }
        s = warp_sum(s);
        if (lane == 0) g_xemb[row] = s + cb[row];
    }
}

// ---------------- K2: mma.sync fp16 scores GEMM + fused softmax + in-loop outW conversion ----
// 256 blocks (bm = (b&31)*128, bn = (b>>5)*128). Each block also converts 512 KB of outW
// to fp16, 32 KB per chunk iteration, hidden under the tensor-bound MMA mainloop.
#define SMEM_DYN (2 * 32768 + 1024)
#define OUTW_F4 (V * 256)            // total float4 elements in outW

__global__ void __launch_bounds__(256, 2) k2_scores(const float* __restrict__ vW,
                                                    const float* __restrict__ outW,
                                                    float* __restrict__ out_attn) {
    extern __shared__ char dsm[];
    __shared__ float sq[128], sv[128], sred[128][2];
    __shared__ bool s_last;

    uint32_t sbase = (smem_u32(dsm) + 1023u) & ~1023u;
    int tid = threadIdx.x, wid = tid >> 5, lane = tid & 31;
    int wm = wid & 3, wn = wid >> 2;
    int bm = (blockIdx.x & 31) * 128, bn = (blockIdx.x >> 5) * 128;

    if (tid < 128) { sq[tid] = g_q[bn + tid]; sv[tid] = vW[bn + tid]; }

    const __half* gA = g_ench + (size_t)bm * 1024;
    const __half* gB = g_uWh + (size_t)bn * 1024;
    const float4* ow4 = (const float4*)outW;
    uint2* owh2 = (uint2*)g_outWh;

    int lr[4], lc[4];
    uint32_t loff[4];
#pragma unroll
    for (int i = 0; i < 4; i++) {
        int idx = tid + 256 * i;
        lr[i] = idx >> 3;
        lc[i] = idx & 7;
        loff[i] = sw((uint32_t)(lr[i] * 128 + lc[i] * 16));
    }

#define LOAD_CHUNK(c, buf) do { \
    uint32_t o_ = (uint32_t)(c) * 64u; \
    uint32_t s_ = sbase + (buf) * 32768u; \
    _Pragma("unroll") \
    for (int i_ = 0; i_ < 4; i_++) { \
        const __half* a_ = gA + (size_t)lr[i_] * 1024 + o_ + lc[i_] * 8; \
        const __half* b_ = gB + (size_t)lr[i_] * 1024 + o_ + lc[i_] * 8; \
        CP_ASYNC16(s_ + loff[i_], a_); \
        CP_ASYNC16(s_ + 16384u + loff[i_], b_); \
    } \
    CP_COMMIT(); \
} while (0)

    float acc[2][8][4] = {};

    LOAD_CHUNK(0, 0);

    uint32_t aRow[2], bRow[4];
#pragma unroll
    for (int mt = 0; mt < 2; mt++)
        aRow[mt] = (uint32_t)((wm * 32 + mt * 16 + (lane & 15)) * 128 + (lane >> 4) * 16);
#pragma unroll
    for (int bp = 0; bp < 4; bp++)
        bRow[bp] = (uint32_t)((wn * 64 + bp * 16 + (lane & 15)) * 128 + (lane >> 4) * 16);

    for (int c = 0; c < NC; c++) {
        if (c + 1 < NC) {
            LOAD_CHUNK(c + 1, (c + 1) & 1);
            CP_WAIT(1);
        } else {
            CP_WAIT(0);
        }
        __syncthreads();
        uint32_t sA = sbase + (uint32_t)(c & 1) * 32768u;
        uint32_t sB = sA + 16384u;
#pragma unroll
        for (int ks = 0; ks < 4; ks++) {
            uint32_t afr[2][4];
#pragma unroll
            for (int mt = 0; mt < 2; mt++)
                LDSM_X4(afr[mt], sA + sw(aRow[mt] + ks * 32));
            uint32_t bfr[4][4];
#pragma unroll
            for (int bp = 0; bp < 4; bp++)
                LDSM_X4(bfr[bp], sB + sw(bRow[bp] + ks * 32));
#pragma unroll
            for (int mt = 0; mt < 2; mt++)
#pragma unroll
                for (int nt = 0; nt < 8; nt++) {
                    uint32_t b0 = bfr[nt >> 1][nt & 1];
                    uint32_t b1 = bfr[nt >> 1][(nt & 1) + 2];
                    mma_f16(acc[mt][nt], afr[mt], b0, b1);
                }
        }
        // ---- in-loop outW fp32->fp16 conversion (hidden under MMA) ----
        {
            int base = (blockIdx.x * NC + c) * 2048 + tid;
#pragma unroll
            for (int h = 0; h < 2; h++) {
                float4 v[4];
#pragma unroll
                for (int j = 0; j < 4; j++) {
                    int idx = base + (h * 4 + j) * 256;
                    if (idx < OUTW_F4) v[j] = ow4[idx];
                }
#pragma unroll
                for (int j = 0; j < 4; j++) {
                    int idx = base + (h * 4 + j) * 256;
                    if (idx < OUTW_F4) {
                        uint2 w = make_uint2(pkh(__float2half_rn(v[j].x), __float2half_rn(v[j].y)),
                                             pkh(__float2half_rn(v[j].z), __float2half_rn(v[j].w)));
                        owh2[idx] = w;
                    }
                }
            }
        }
        __syncthreads();
    }

    // ---- epilogue: weighted tanh row reduction ----
    int cb2 = wn * 64;
    int c0 = 2 * (lane & 3);
    float p[2][2];
#pragma unroll
    for (int mt = 0; mt < 2; mt++)
#pragma unroll
        for (int half = 0; half < 2; half++) {
            float s = 0.f;
#pragma unroll
            for (int nt = 0; nt < 8; nt++) {
#pragma unroll
                for (int j = 0; j < 2; j++) {
                    int n = cb2 + nt * 8 + c0 + j;
                    s += sv[n] * tanhf(sq[n] + acc[mt][nt][half * 2 + j]);
                }
            }
            p[mt][half] = s;
        }
#pragma unroll
    for (int mt = 0; mt < 2; mt++)
#pragma unroll
        for (int half = 0; half < 2; half++) {
            float s = p[mt][half];
            s += __shfl_xor_sync(0xffffffffu, s, 1);
            s += __shfl_xor_sync(0xffffffffu, s, 2);
            p[mt][half] = s;
        }
    if ((lane & 3) == 0) {
#pragma unroll
        for (int mt = 0; mt < 2; mt++)
#pragma unroll
            for (int half = 0; half < 2; half++)
                sred[wm * 32 + mt * 16 + half * 8 + (lane >> 2)][wn] = p[mt][half];
    }
    __syncthreads();
    if (tid < 128)
        atomicAdd(&g_scores[bm + tid], sred[tid][0] + sred[tid][1]);

    // ---- fused softmax in last-finishing MMA block ----
    __threadfence();
    __syncthreads();
    if (tid == 0) s_last = (atomicAdd(&g_k2cnt, 1u) == 255u);
    __syncthreads();
    if (!s_last) return;
    if (tid == 0) g_k2cnt = 0u;
    float v[16];
    float mx = -1e30f;
#pragma unroll
    for (int i = 0; i < 16; i++) {
        v[i] = g_scores[tid + 256 * i];
        mx = fmaxf(mx, v[i]);
    }
    mx = warp_max(mx);
    if (lane == 0) sq[wid] = mx;
    __syncthreads();
    if (tid < 32) {
        float m2 = (tid < 8) ? sq[tid] : -1e30f;
        m2 = warp_max(m2);
        if (tid == 0) sq[0] = m2;
    }
    __syncthreads();
    mx = sq[0];
    float se = 0.f;
#pragma unroll
    for (int i = 0; i < 16; i++) {
        v[i] = expf(v[i] - mx);
        se += v[i];
    }
    se = warp_sum(se);
    if (lane == 0) sv[wid] = se;
    __syncthreads();
    if (tid < 32) {
        float s2 = (tid < 8) ? sv[tid] : 0.f;
        s2 = warp_sum(s2);
        if (tid == 0) sv[0] = s2;
    }
    __syncthreads();
    float inv = 1.f / sv[0];
#pragma unroll
    for (int i = 0; i < 16; i++) {
        float a = v[i] * inv;
        g_attn[tid + 256 * i] = a;
        out_attn[tid + 256 * i] = a;
    }
}

// ---------------- K_EPI: persistent fused epilogue (context -> combine -> GRU) ----------------
__global__ void __launch_bounds__(1024) k_epi(const float* __restrict__ cW,
                                              const float* __restrict__ w_ih,
                                              const float* __restrict__ b_ih,
                                              const float* __restrict__ hprev,
                                              float* __restrict__ d_out) {
    __shared__ float aw[64];
    __shared__ float2 sbuf[3 * 256];
    __shared__ float s32[32];
    __shared__ unsigned s_gen0;
    int t = threadIdx.x, wid = t >> 5, lane = t & 31;
    int b = blockIdx.x;

    if (t == 0) s_gen0 = g_bar_gen;

    // ---- Phase A: context partials ----
    int bg = b >> 1, ch = b & 1;
    int ci = t & 255;
    int c2 = ch * 256 + ci;
    int rh = t >> 8;
    int l0 = bg * 64 + rh * 16;
    if (t < 64) aw[t] = g_attn[bg * 64 + t];
    __syncthreads();
    unsigned gen0 = s_gen0;
    {
        float s0 = 0.f, s1 = 0.f;
        const float* awh = aw + rh * 16;
#pragma unroll
        for (int bb = 0; bb < 2; bb++) {
            uint32_t e[8];
#pragma unroll
            for (int l = 0; l < 8; l++)
                e[l] = *(const uint32_t*)(g_ench + (size_t)(l0 + bb * 8 + l) * 1024 + 2 * c2);
#pragma unroll
            for (int l = 0; l < 8; l++) {
                float w = awh[bb * 8 + l];
                float2 f = __half22float2(*(__half2*)&e[l]);
                s0 += w * f.x;
                s1 += w * f.y;
            }
        }
        if (rh > 0) sbuf[(rh - 1) * 256 + ci] = make_float2(s0, s1);
        __syncthreads();
        if (rh == 0) {
            float2 a1 = sbuf[ci], a2 = sbuf[256 + ci], a3 = sbuf[512 + ci];
            *(float2*)&g_cpart[bg * H + 2 * c2] =
                make_float2(s0 + a1.x + a2.x + a3.x, s1 + a1.y + a2.y + a3.y);
        }
    }
    grid_sync_128(gen0 + 1);

    // ---- Phase B: distributed context reduce ----
    if (t < 512) {
        int col = b * 8 + (t >> 6);
        int p = t & 63;
        float s = g_cpart[p * H + col];
        s = warp_sum(s);
        if (lane == 0) s32[wid] = s;
    }
    __syncthreads();
    if (t < 8) g_context[b * 8 + t] = s32[2 * t] + s32[2 * t + 1];
    grid_sync_128(gen0 + 2);

    // ---- Phase C: x = relu(cW_ctx@ctx + xemb), 4 warps/row ----
    {
        int task = b * 32 + wid;
        int row = task >> 2, q = task & 3;
        const float4* wr = (const float4*)(cW + (size_t)row * 2 * H + q * 256);
        const float4* vec = (const float4*)(g_context + q * 256);
        float s = 0.f;
#pragma unroll
        for (int i = 0; i < 2; i++) {
            float4 a = wr[lane + 32 * i];
            float4 v = vec[lane + 32 * i];
            s += a.x * v.x + a.y * v.y + a.z * v.z + a.w * v.w;
        }
        s = warp_sum(s);
        if (lane == 0) s32[wid] = s;
        __syncthreads();
        if (t < 8) {
            int row2 = b * 8 + t;
            g_x[row2] = fmaxf(s32[4 * t] + s32[4 * t + 1] + s32[4 * t + 2] + s32[4 * t + 3]
                              + g_xemb[row2], 0.f);
        }
    }
    grid_sync_128(gen0 + 3);

    // ---- Phase D: gi rows grouped per GRU element + block-local GRU/residual ----
    {
        float s = 0.f;
        if (wid < 24) {
            int g = wid >> 3, rr = wid & 7;
            int row = g * H + b * 8 + rr;
            const float4* wr = (const float4*)(w_ih + (size_t)row * H);
            const float4* vec = (const float4*)g_x;
#pragma unroll
            for (int i = 0; i < 8; i++) {
                float4 a = wr[lane + 32 * i];
                float4 v = vec[lane + 32 * i];
                s += a.x * v.x + a.y * v.y + a.z * v.z + a.w * v.w;
            }
            s = warp_sum(s);
            if (lane == 0) s32[wid] = s;
        }
        __syncthreads();
        if (t < 8) {
            int i = b * 8 + t;
            float ir = s32[t] + b_ih[i];
            float iz = s32[8 + t] + b_ih[H + i];
            float inn = s32[16 + t] + b_ih[2 * H + i];
            float r = 1.f / (1.f + expf(-(ir + g_gh[i])));
            float z = 1.f / (1.f + expf(-(iz + g_gh[H + i])));
            float n = tanhf(inn + r * g_gh[2 * H + i]);
            float hp = hprev[i];
            float h = (1.f - z) * n + z * hp;
            d_out[V + i] = h;
            g_ov[i] = g_context[i] + h;
        }
    }
}

// ---------------- K8: logits = outWh(fp16) @ ov + outb, 2 rows/warp (MLP=8) ----------------
__global__ void __launch_bounds__(256) k8_logits(const float* __restrict__ outb,
                                                 float* __restrict__ d_out) {
    __shared__ float4 ov[H / 4];
    int t = threadIdx.x;
    ov[t] = ((const float4*)g_ov)[t];
    __syncthreads();
    int warp = t >> 5, lane = t & 31;
    int v0 = blockIdx.x * 16 + warp * 2;
    const uint4* w0 = (const uint4*)(g_outWh + (size_t)v0 * 1024);
    const uint4* w1 = (const uint4*)(g_outWh + (size_t)(v0 + 1) * 1024);
    uint4 a[4], b[4];
#pragma unroll
    for (int i = 0; i < 4; i++) {
        a[i] = w0[lane + 32 * i];
        b[i] = w1[lane + 32 * i];
    }
    float s0 = 0.f, s1 = 0.f;
#pragma unroll
    for (int i = 0; i < 4; i++) {
        int u = lane + 32 * i;
        float4 o0 = ov[2 * u], o1 = ov[2 * u + 1];
        {
            float2 f0 = __half22float2(*(__half2*)&a[i].x);
            float2 f1 = __half22float2(*(__half2*)&a[i].y);
            float2 f2 = __half22float2(*(__half2*)&a[i].z);
            float2 f3 = __half22float2(*(__half2*)&a[i].w);
            s0 += f0.x * o0.x + f0.y * o0.y + f1.x * o0.z + f1.y * o0.w
                + f2.x * o1.x + f2.y * o1.y + f3.x * o1.z + f3.y * o1.w;
        }
        {
            float2 f0 = __half22float2(*(__half2*)&b[i].x);
            float2 f1 = __half22float2(*(__half2*)&b[i].y);
            float2 f2 = __half22float2(*(__half2*)&b[i].z);
            float2 f3 = __half22float2(*(__half2*)&b[i].w);
            s1 += f0.x * o0.x + f0.y * o0.y + f1.x * o0.z + f1.y * o0.w
                + f2.x * o1.x + f2.y * o1.y + f3.x * o1.z + f3.y * o1.w;
        }
    }
    s0 = warp_sum(s0);
    s1 = warp_sum(s1);
    if (lane == 0) {
        d_out[v0] = s0 + outb[v0];
        d_out[v0 + 1] = s1 + outb[v0 + 1];
    }
}

// ---------------- launch ----------------
extern "C" void kernel_launch(void* const* d_in, const int* in_sizes, int n_in,
                              void* d_out, int out_size) {
    const int* tok = (const int*)d_in[0];
    const float* hidden = (const float*)d_in[1];
    const float* enc = (const float*)d_in[2];
    const float* emb = (const float*)d_in[3];
    const float* wW = (const float*)d_in[4];
    const float* wb = (const float*)d_in[5];
    const float* uW = (const float*)d_in[6];
    const float* ub = (const float*)d_in[7];
    const float* vW = (const float*)d_in[8];
    const float* cW = (const float*)d_in[9];
    const float* cb = (const float*)d_in[10];
    const float* w_ih = (const float*)d_in[11];
    const float* b_ih = (const float*)d_in[12];
    const float* w_hh = (const float*)d_in[13];
    const float* b_hh = (const float*)d_in[14];
    const float* outW = (const float*)d_in[15];
    const float* outb = (const float*)d_in[16];
    float* out = (float*)d_out;

    cudaFuncSetAttribute(k2_scores, cudaFuncAttributeMaxDynamicSharedMemorySize, SMEM_DYN);

    k_prologue<<<PRO_BLOCKS, 256>>>(enc, uW, hidden, wW, wb, ub, w_hh, b_hh,
                                    cW, cb, emb, tok);
    k2_scores<<<256, 256, SMEM_DYN>>>(vW, outW, out + V + H);
    k_epi<<<128, 1024>>>(cW, w_ih, b_ih, hidden, out);
    k8_logits<<<V / 16, 256>>>(outb, out);
}

// round 15
// speedup vs baseline: 1.2773x; 1.2773x over previous
#include <cuda_runtime.h>
#include <cuda_fp16.h>
#include <math.h>
#include <stdint.h>

#define H 1024
#define V 32000
#define L 4096
#define NC 16            // K chunks of 64 fp16 over K=1024

// ---------------- device scratch ----------------
__device__ __half g_ench[(size_t)L * 1024];   // enc fp16, 8 MB
__device__ __half g_uWh[(size_t)H * 1024];    // uW fp16, 2 MB
__device__ float g_cpart[64 * H];
__device__ float g_scores[L];
__device__ float g_q[H];
__device__ float g_attn[L];
__device__ float g_context[H];
__device__ float g_x[H];
__device__ float g_xemb[H];      // cW_emb @ embedded + cb (prologue)
__device__ float g_gi[3 * H];
__device__ float g_gh[3 * H];
__device__ float g_ov[H];
__device__ unsigned g_k2cnt;
__device__ unsigned g_bar_cnt;
__device__ volatile unsigned g_bar_gen;

// ---------------- helpers ----------------
__device__ __forceinline__ uint32_t smem_u32(const void* p) {
    uint32_t a;
    asm("{ .reg .u64 t; cvta.to.shared.u64 t, %1; cvt.u32.u64 %0, t; }" : "=r"(a) : "l"(p));
    return a;
}
__device__ __forceinline__ uint32_t sw(uint32_t off) {   // Swizzle<3,4,3> on 128B rows
    return off ^ ((off >> 3) & 0x70u);
}
#define CP_ASYNC16(dst, src) \
    asm volatile("cp.async.cg.shared.global [%0], [%1], 16;" :: "r"(dst), "l"(src) : "memory")
#define CP_COMMIT() asm volatile("cp.async.commit_group;" ::: "memory")
#define CP_WAIT(n)  asm volatile("cp.async.wait_group %0;" :: "n"(n) : "memory")
#define LDSM_X4(r, a) \
    asm volatile("ldmatrix.sync.aligned.m8n8.x4.shared.b16 {%0,%1,%2,%3}, [%4];" \
                 : "=r"((r)[0]), "=r"((r)[1]), "=r"((r)[2]), "=r"((r)[3]) : "r"(a))

__device__ __forceinline__ void mma_f16(float* c, const uint32_t* a, uint32_t b0, uint32_t b1) {
    asm volatile("mma.sync.aligned.m16n8k16.row.col.f32.f16.f16.f32 "
                 "{%0,%1,%2,%3}, {%4,%5,%6,%7}, {%8,%9}, {%0,%1,%2,%3};"
                 : "+f"(c[0]), "+f"(c[1]), "+f"(c[2]), "+f"(c[3])
                 : "r"(a[0]), "r"(a[1]), "r"(a[2]), "r"(a[3]), "r"(b0), "r"(b1));
}

__device__ __forceinline__ float warp_sum(float v) {
#pragma unroll
    for (int o = 16; o; o >>= 1) v += __shfl_xor_sync(0xffffffffu, v, o);
    return v;
}
__device__ __forceinline__ float warp_max(float v) {
#pragma unroll
    for (int o = 16; o; o >>= 1) v = fmaxf(v, __shfl_xor_sync(0xffffffffu, v, o));
    return v;
}
__device__ __forceinline__ uint32_t pkh(__half a, __half b) {
    uint16_t ua = *(uint16_t*)&a, ub = *(uint16_t*)&b;
    return (uint32_t)ua | ((uint32_t)ub << 16);
}

// grid-wide barrier for 128 co-resident blocks
__device__ __forceinline__ void grid_sync_128(unsigned target) {
    __threadfence();
    __syncthreads();
    if (threadIdx.x == 0) {
        unsigned v = atomicAdd(&g_bar_cnt, 1u);
        if (v == 127u) {
            g_bar_cnt = 0u;
            __threadfence();
            g_bar_gen = target;
        } else {
            while ((int)(g_bar_gen - target) < 0) {}
            __threadfence();
        }
    }
    __syncthreads();
}

// ---------------- fused prologue ----------------
#define PRO_BLOCKS (L + H + 128 + 384 + 128)

__global__ void __launch_bounds__(256) k_prologue(const float* __restrict__ enc,
                                                  const float* __restrict__ uW,
                                                  const float* __restrict__ h0,
                                                  const float* __restrict__ wW,
                                                  const float* __restrict__ wb,
                                                  const float* __restrict__ ub,
                                                  const float* __restrict__ w_hh,
                                                  const float* __restrict__ b_hh,
                                                  const float* __restrict__ cW,
                                                  const float* __restrict__ cb,
                                                  const float* __restrict__ emb,
                                                  const int* __restrict__ tok) {
    int b = blockIdx.x;
    int tid = threadIdx.x;
    if (b < L + H) {
        bool isA = (b < L);
        int r = isA ? b : b - L;
        if (isA && tid == 0) g_scores[r] = 0.f;
        const float4* src = (const float4*)((isA ? enc : uW) + (size_t)r * H);
        float4 v = src[tid];
        uint2 w = make_uint2(pkh(__float2half_rn(v.x), __float2half_rn(v.y)),
                             pkh(__float2half_rn(v.z), __float2half_rn(v.w)));
        __half* dst = (isA ? g_ench : g_uWh) + (size_t)r * 1024;
        ((uint2*)dst)[tid] = w;
    } else if (b < L + H + 128) {
        int warp = ((b - L - H) << 3) + (tid >> 5);
        int lane = tid & 31;
        const float4* row = (const float4*)(wW + (size_t)warp * H);
        const float4* h4 = (const float4*)h0;
        float s = 0.f;
#pragma unroll
        for (int i = 0; i < 8; i++) {
            float4 a = row[lane + 32 * i];
            float4 hh = h4[lane + 32 * i];
            s += a.x * hh.x + a.y * hh.y + a.z * hh.z + a.w * hh.w;
        }
        s = warp_sum(s);
        if (lane == 0) g_q[warp] = s + wb[warp] + ub[warp];
    } else if (b < L + H + 512) {
        int idx = ((b - L - H - 128) << 3) + (tid >> 5);   // 0..3071
        int lane = tid & 31;
        const float4* row = (const float4*)(w_hh + (size_t)idx * H);
        const float4* h4 = (const float4*)h0;
        float s = 0.f;
#pragma unroll
        for (int i = 0; i < 8; i++) {
            float4 a = row[lane + 32 * i];
            float4 hh = h4[lane + 32 * i];
            s += a.x * hh.x + a.y * hh.y + a.z * hh.z + a.w * hh.w;
        }
        s = warp_sum(s);
        if (lane == 0) g_gh[idx] = s + b_hh[idx];
    } else {
        int row = ((b - L - H - 512) << 3) + (tid >> 5);   // 0..1023
        int lane = tid & 31;
        const float4* wr = (const float4*)(cW + (size_t)row * 2 * H + H);
        const float4* e4 = (const float4*)(emb + (size_t)tok[0] * H);
        float s = 0.f;
#pragma unroll
        for (int i = 0; i < 8; i++) {
            float4 a = wr[lane + 32 * i];
            float4 e = e4[lane + 32 * i];
            s += a.x * e.x + a.y * e.y + a.z * e.z + a.w * e.w;
        }
        s = warp_sum(s);
        if (lane == 0) g_xemb[row] = s + cb[row];
    }
}

// ---------------- K2: mma.sync fp16 scores GEMM (K=1024) + fused softmax ----------------
#define SMEM_DYN (2 * 32768 + 1024)

__global__ void __launch_bounds__(256, 2) k2_scores(const float* __restrict__ vW,
                                                    float* __restrict__ out_attn) {
    extern __shared__ char dsm[];
    __shared__ float sq[128], sv[128], sred[128][2];
    __shared__ bool s_last;

    uint32_t sbase = (smem_u32(dsm) + 1023u) & ~1023u;
    int tid = threadIdx.x, wid = tid >> 5, lane = tid & 31;
    int wm = wid & 3, wn = wid >> 2;
    int bm = blockIdx.x * 128, bn = blockIdx.y * 128;

    if (tid < 128) { sq[tid] = g_q[bn + tid]; sv[tid] = vW[bn + tid]; }

    const __half* gA = g_ench + (size_t)bm * 1024;
    const __half* gB = g_uWh + (size_t)bn * 1024;

    int lr[4], lc[4];
    uint32_t loff[4];
#pragma unroll
    for (int i = 0; i < 4; i++) {
        int idx = tid + 256 * i;
        lr[i] = idx >> 3;
        lc[i] = idx & 7;
        loff[i] = sw((uint32_t)(lr[i] * 128 + lc[i] * 16));
    }

#define LOAD_CHUNK(c, buf) do { \
    uint32_t o_ = (uint32_t)(c) * 64u; \
    uint32_t s_ = sbase + (buf) * 32768u; \
    _Pragma("unroll") \
    for (int i_ = 0; i_ < 4; i_++) { \
        const __half* a_ = gA + (size_t)lr[i_] * 1024 + o_ + lc[i_] * 8; \
        const __half* b_ = gB + (size_t)lr[i_] * 1024 + o_ + lc[i_] * 8; \
        CP_ASYNC16(s_ + loff[i_], a_); \
        CP_ASYNC16(s_ + 16384u + loff[i_], b_); \
    } \
    CP_COMMIT(); \
} while (0)

    float acc[2][8][4] = {};

    LOAD_CHUNK(0, 0);

    uint32_t aRow[2], bRow[4];
#pragma unroll
    for (int mt = 0; mt < 2; mt++)
        aRow[mt] = (uint32_t)((wm * 32 + mt * 16 + (lane & 15)) * 128 + (lane >> 4) * 16);
#pragma unroll
    for (int bp = 0; bp < 4; bp++)
        bRow[bp] = (uint32_t)((wn * 64 + bp * 16 + (lane & 15)) * 128 + (lane >> 4) * 16);

    for (int c = 0; c < NC; c++) {
        if (c + 1 < NC) {
            LOAD_CHUNK(c + 1, (c + 1) & 1);
            CP_WAIT(1);
        } else {
            CP_WAIT(0);
        }
        __syncthreads();
        uint32_t sA = sbase + (uint32_t)(c & 1) * 32768u;
        uint32_t sB = sA + 16384u;
#pragma unroll
        for (int ks = 0; ks < 4; ks++) {
            uint32_t afr[2][4];
#pragma unroll
            for (int mt = 0; mt < 2; mt++)
                LDSM_X4(afr[mt], sA + sw(aRow[mt] + ks * 32));
            uint32_t bfr[4][4];
#pragma unroll
            for (int bp = 0; bp < 4; bp++)
                LDSM_X4(bfr[bp], sB + sw(bRow[bp] + ks * 32));
#pragma unroll
            for (int mt = 0; mt < 2; mt++)
#pragma unroll
                for (int nt = 0; nt < 8; nt++) {
                    uint32_t b0 = bfr[nt >> 1][nt & 1];
                    uint32_t b1 = bfr[nt >> 1][(nt & 1) + 2];
                    mma_f16(acc[mt][nt], afr[mt], b0, b1);
                }
        }
        __syncthreads();
    }

    // ---- epilogue: weighted tanh row reduction ----
    int cb2 = wn * 64;
    int c0 = 2 * (lane & 3);
    float p[2][2];
#pragma unroll
    for (int mt = 0; mt < 2; mt++)
#pragma unroll
        for (int half = 0; half < 2; half++) {
            float s = 0.f;
#pragma unroll
            for (int nt = 0; nt < 8; nt++) {
#pragma unroll
                for (int j = 0; j < 2; j++) {
                    int n = cb2 + nt * 8 + c0 + j;
                    s += sv[n] * tanhf(sq[n] + acc[mt][nt][half * 2 + j]);
                }
            }
            p[mt][half] = s;
        }
#pragma unroll
    for (int mt = 0; mt < 2; mt++)
#pragma unroll
        for (int half = 0; half < 2; half++) {
            float s = p[mt][half];
            s += __shfl_xor_sync(0xffffffffu, s, 1);
            s += __shfl_xor_sync(0xffffffffu, s, 2);
            p[mt][half] = s;
        }
    if ((lane & 3) == 0) {
#pragma unroll
        for (int mt = 0; mt < 2; mt++)
#pragma unroll
            for (int half = 0; half < 2; half++)
                sred[wm * 32 + mt * 16 + half * 8 + (lane >> 2)][wn] = p[mt][half];
    }
    __syncthreads();
    if (tid < 128)
        atomicAdd(&g_scores[bm + tid], sred[tid][0] + sred[tid][1]);

    // ---- fused softmax in last-finishing block ----
    __threadfence();
    __syncthreads();
    if (tid == 0) s_last = (atomicAdd(&g_k2cnt, 1u) == (unsigned)(32 * 8 - 1));
    __syncthreads();
    if (!s_last) return;
    if (tid == 0) g_k2cnt = 0u;
    float v[16];
    float mx = -1e30f;
#pragma unroll
    for (int i = 0; i < 16; i++) {
        v[i] = g_scores[tid + 256 * i];
        mx = fmaxf(mx, v[i]);
    }
    mx = warp_max(mx);
    if (lane == 0) sq[wid] = mx;
    __syncthreads();
    if (tid < 32) {
        float m2 = (tid < 8) ? sq[tid] : -1e30f;
        m2 = warp_max(m2);
        if (tid == 0) sq[0] = m2;
    }
    __syncthreads();
    mx = sq[0];
    float se = 0.f;
#pragma unroll
    for (int i = 0; i < 16; i++) {
        v[i] = expf(v[i] - mx);
        se += v[i];
    }
    se = warp_sum(se);
    if (lane == 0) sv[wid] = se;
    __syncthreads();
    if (tid < 32) {
        float s2 = (tid < 8) ? sv[tid] : 0.f;
        s2 = warp_sum(s2);
        if (tid == 0) sv[0] = s2;
    }
    __syncthreads();
    float inv = 1.f / sv[0];
#pragma unroll
    for (int i = 0; i < 16; i++) {
        float a = v[i] * inv;
        g_attn[tid + 256 * i] = a;
        out_attn[tid + 256 * i] = a;
    }
}

// ---------------- K_EPI: persistent fused epilogue (context -> combine -> GRU) ----------------
__global__ void __launch_bounds__(1024) k_epi(const float* __restrict__ cW,
                                              const float* __restrict__ w_ih,
                                              const float* __restrict__ b_ih,
                                              const float* __restrict__ hprev,
                                              float* __restrict__ d_out) {
    __shared__ float aw[64];
    __shared__ float2 sbuf[3 * 256];
    __shared__ float s32[32];
    __shared__ unsigned s_gen0;
    int t = threadIdx.x, wid = t >> 5, lane = t & 31;
    int b = blockIdx.x;

    if (t == 0) s_gen0 = g_bar_gen;

    // ---- Phase A: context partials ----
    int bg = b >> 1, ch = b & 1;
    int ci = t & 255;
    int c2 = ch * 256 + ci;
    int rh = t >> 8;
    int l0 = bg * 64 + rh * 16;
    if (t < 64) aw[t] = g_attn[bg * 64 + t];
    __syncthreads();
    unsigned gen0 = s_gen0;
    {
        float s0 = 0.f, s1 = 0.f;
        const float* awh = aw + rh * 16;
#pragma unroll
        for (int bb = 0; bb < 2; bb++) {
            uint32_t e[8];
#pragma unroll
            for (int l = 0; l < 8; l++)
                e[l] = *(const uint32_t*)(g_ench + (size_t)(l0 + bb * 8 + l) * 1024 + 2 * c2);
#pragma unroll
            for (int l = 0; l < 8; l++) {
                float w = awh[bb * 8 + l];
                float2 f = __half22float2(*(__half2*)&e[l]);
                s0 += w * f.x;
                s1 += w * f.y;
            }
        }
        if (rh > 0) sbuf[(rh - 1) * 256 + ci] = make_float2(s0, s1);
        __syncthreads();
        if (rh == 0) {
            float2 a1 = sbuf[ci], a2 = sbuf[256 + ci], a3 = sbuf[512 + ci];
            *(float2*)&g_cpart[bg * H + 2 * c2] =
                make_float2(s0 + a1.x + a2.x + a3.x, s1 + a1.y + a2.y + a3.y);
        }
    }
    grid_sync_128(gen0 + 1);

    // ---- Phase B: distributed context reduce ----
    if (t < 512) {
        int col = b * 8 + (t >> 6);
        int p = t & 63;
        float s = g_cpart[p * H + col];
        s = warp_sum(s);
        if (lane == 0) s32[wid] = s;
    }
    __syncthreads();
    if (t < 8) g_context[b * 8 + t] = s32[2 * t] + s32[2 * t + 1];
    grid_sync_128(gen0 + 2);

    // ---- Phase C: x = relu(cW_ctx@ctx + xemb), 4 warps/row ----
    {
        int task = b * 32 + wid;
        int row = task >> 2, q = task & 3;
        const float4* wr = (const float4*)(cW + (size_t)row * 2 * H + q * 256);
        const float4* vec = (const float4*)(g_context + q * 256);
        float s = 0.f;
#pragma unroll
        for (int i = 0; i < 2; i++) {
            float4 a = wr[lane + 32 * i];
            float4 v = vec[lane + 32 * i];
            s += a.x * v.x + a.y * v.y + a.z * v.z + a.w * v.w;
        }
        s = warp_sum(s);
        if (lane == 0) s32[wid] = s;
        __syncthreads();
        if (t < 8) {
            int row2 = b * 8 + t;
            g_x[row2] = fmaxf(s32[4 * t] + s32[4 * t + 1] + s32[4 * t + 2] + s32[4 * t + 3]
                              + g_xemb[row2], 0.f);
        }
    }
    grid_sync_128(gen0 + 3);

    // ---- Phase D: gi rows grouped per GRU element + block-local GRU/residual ----
    {
        float s = 0.f;
        if (wid < 24) {
            int g = wid >> 3, rr = wid & 7;
            int row = g * H + b * 8 + rr;
            const float4* wr = (const float4*)(w_ih + (size_t)row * H);
            const float4* vec = (const float4*)g_x;
#pragma unroll
            for (int i = 0; i < 8; i++) {
                float4 a = wr[lane + 32 * i];
                float4 v = vec[lane + 32 * i];
                s += a.x * v.x + a.y * v.y + a.z * v.z + a.w * v.w;
            }
            s = warp_sum(s);
            if (lane == 0) s32[wid] = s;
        }
        __syncthreads();
        if (t < 8) {
            int i = b * 8 + t;
            float ir = s32[t] + b_ih[i];
            float iz = s32[8 + t] + b_ih[H + i];
            float inn = s32[16 + t] + b_ih[2 * H + i];
            float r = 1.f / (1.f + expf(-(ir + g_gh[i])));
            float z = 1.f / (1.f + expf(-(iz + g_gh[H + i])));
            float n = tanhf(inn + r * g_gh[2 * H + i]);
            float hp = hprev[i];
            float h = (1.f - z) * n + z * hp;
            d_out[V + i] = h;
            g_ov[i] = g_context[i] + h;
        }
    }
}

// ---------------- K8: logits = outW @ ov + outb, 2 rows/warp (MLP=16) ----------------
__global__ void __launch_bounds__(256) k8_logits(const float* __restrict__ outW,
                                                 const float* __restrict__ outb,
                                                 float* __restrict__ d_out) {
    __shared__ float4 ov[H / 4];
    int t = threadIdx.x;
    ov[t] = ((const float4*)g_ov)[t];
    __syncthreads();
    int warp = t >> 5, lane = t & 31;
    int v0 = blockIdx.x * 16 + warp * 2;
    const float4* w0 = (const float4*)(outW + (size_t)v0 * H);
    const float4* w1 = (const float4*)(outW + (size_t)(v0 + 1) * H);
    float4 a[8], b[8];
#pragma unroll
    for (int i = 0; i < 8; i++) {
        a[i] = w0[lane + 32 * i];
        b[i] = w1[lane + 32 * i];
    }
    float s0 = 0.f, s1 = 0.f;
#pragma unroll
    for (int i = 0; i < 8; i++) {
        float4 o = ov[lane + 32 * i];
        s0 += a[i].x * o.x + a[i].y * o.y + a[i].z * o.z + a[i].w * o.w;
        s1 += b[i].x * o.x + b[i].y * o.y + b[i].z * o.z + b[i].w * o.w;
    }
    s0 = warp_sum(s0);
    s1 = warp_sum(s1);
    if (lane == 0) {
        d_out[v0] = s0 + outb[v0];
        d_out[v0 + 1] = s1 + outb[v0 + 1];
    }
}

// ---------------- launch ----------------
extern "C" void kernel_launch(void* const* d_in, const int* in_sizes, int n_in,
                              void* d_out, int out_size) {
    const int* tok = (const int*)d_in[0];
    const float* hidden = (const float*)d_in[1];
    const float* enc = (const float*)d_in[2];
    const float* emb = (const float*)d_in[3];
    const float* wW = (const float*)d_in[4];
    const float* wb = (const float*)d_in[5];
    const float* uW = (const float*)d_in[6];
    const float* ub = (const float*)d_in[7];
    const float* vW = (const float*)d_in[8];
    const float* cW = (const float*)d_in[9];
    const float* cb = (const float*)d_in[10];
    const float* w_ih = (const float*)d_in[11];
    const float* b_ih = (const float*)d_in[12];
    const float* w_hh = (const float*)d_in[13];
    const float* b_hh = (const float*)d_in[14];
    const float* outW = (const float*)d_in[15];
    const float* outb = (const float*)d_in[16];
    float* out = (float*)d_out;

    cudaFuncSetAttribute(k2_scores, cudaFuncAttributeMaxDynamicSharedMemorySize, SMEM_DYN);

    k_prologue<<<PRO_BLOCKS, 256>>>(enc, uW, hidden, wW, wb, ub, w_hh, b_hh,
                                    cW, cb, emb, tok);
    k2_scores<<<dim3(L / 128, H / 128), 256, SMEM_DYN>>>(vW, out + V + H);
    k_epi<<<128, 1024>>>(cW, w_ih, b_ih, hidden, out);
    k8_logits<<<V / 16, 256>>>(outW, outb, out);
}

// round 16
// speedup vs baseline: 1.3156x; 1.0300x over previous
#include <cuda_runtime.h>
#include <cuda_fp16.h>
#include <math.h>
#include <stdint.h>

#define H 1024
#define V 32000
#define L 4096
#define NC 16            // K chunks of 64 fp16 over K=1024

// ---------------- device scratch ----------------
__device__ __half g_ench[(size_t)L * 1024];   // enc fp16, 8 MB
__device__ __half g_uWh[(size_t)H * 1024];    // uW fp16, 2 MB
__device__ float g_cpart[64 * H];
__device__ float g_scores[L];
__device__ float g_q[H];
__device__ float g_attn[L];
__device__ float g_context[H];
__device__ float g_x[H];
__device__ float g_xemb[H];      // cW_emb @ embedded + cb (filler blocks in k2)
__device__ float g_gi[3 * H];
__device__ float g_gh[3 * H];    // w_hh @ hprev + b_hh (filler blocks in k2)
__device__ float g_ov[H];
__device__ unsigned g_k2cnt;
__device__ unsigned g_bar_cnt;
__device__ volatile unsigned g_bar_gen;

// ---------------- helpers ----------------
__device__ __forceinline__ uint32_t smem_u32(const void* p) {
    uint32_t a;
    asm("{ .reg .u64 t; cvta.to.shared.u64 t, %1; cvt.u32.u64 %0, t; }" : "=r"(a) : "l"(p));
    return a;
}
__device__ __forceinline__ uint32_t sw(uint32_t off) {   // Swizzle<3,4,3> on 128B rows
    return off ^ ((off >> 3) & 0x70u);
}
#define CP_ASYNC16(dst, src) \
    asm volatile("cp.async.cg.shared.global [%0], [%1], 16;" :: "r"(dst), "l"(src) : "memory")
#define CP_COMMIT() asm volatile("cp.async.commit_group;" ::: "memory")
#define CP_WAIT(n)  asm volatile("cp.async.wait_group %0;" :: "n"(n) : "memory")
#define LDSM_X4(r, a) \
    asm volatile("ldmatrix.sync.aligned.m8n8.x4.shared.b16 {%0,%1,%2,%3}, [%4];" \
                 : "=r"((r)[0]), "=r"((r)[1]), "=r"((r)[2]), "=r"((r)[3]) : "r"(a))

__device__ __forceinline__ void mma_f16(float* c, const uint32_t* a, uint32_t b0, uint32_t b1) {
    asm volatile("mma.sync.aligned.m16n8k16.row.col.f32.f16.f16.f32 "
                 "{%0,%1,%2,%3}, {%4,%5,%6,%7}, {%8,%9}, {%0,%1,%2,%3};"
                 : "+f"(c[0]), "+f"(c[1]), "+f"(c[2]), "+f"(c[3])
                 : "r"(a[0]), "r"(a[1]), "r"(a[2]), "r"(a[3]), "r"(b0), "r"(b1));
}

__device__ __forceinline__ float warp_sum(float v) {
#pragma unroll
    for (int o = 16; o; o >>= 1) v += __shfl_xor_sync(0xffffffffu, v, o);
    return v;
}
__device__ __forceinline__ float warp_max(float v) {
#pragma unroll
    for (int o = 16; o; o >>= 1) v = fmaxf(v, __shfl_xor_sync(0xffffffffu, v, o));
    return v;
}
__device__ __forceinline__ uint32_t pkh(__half a, __half b) {
    uint16_t ua = *(uint16_t*)&a, ub = *(uint16_t*)&b;
    return (uint32_t)ua | ((uint32_t)ub << 16);
}

// grid-wide barrier for 128 co-resident blocks
__device__ __forceinline__ void grid_sync_128(unsigned target) {
    __threadfence();
    __syncthreads();
    if (threadIdx.x == 0) {
        unsigned v = atomicAdd(&g_bar_cnt, 1u);
        if (v == 127u) {
            g_bar_cnt = 0u;
            __threadfence();
            g_bar_gen = target;
        } else {
            while ((int)(g_bar_gen - target) < 0) {}
            __threadfence();
        }
    }
    __syncthreads();
}

// ---------------- fused prologue (conversions + k1 only) ----------------
// blocks [0,L): enc row -> fp16, zero g_scores[b]
// blocks [L,L+H): uW row -> fp16
// blocks [L+H, +128): k1: q = wW@h0 + wb + ub (8 rows/block)
#define PRO_BLOCKS (L + H + 128)

__global__ void __launch_bounds__(256) k_prologue(const float* __restrict__ enc,
                                                  const float* __restrict__ uW,
                                                  const float* __restrict__ h0,
                                                  const float* __restrict__ wW,
                                                  const float* __restrict__ wb,
                                                  const float* __restrict__ ub) {
    int b = blockIdx.x;
    int tid = threadIdx.x;
    if (b < L + H) {
        bool isA = (b < L);
        int r = isA ? b : b - L;
        if (isA && tid == 0) g_scores[r] = 0.f;
        const float4* src = (const float4*)((isA ? enc : uW) + (size_t)r * H);
        float4 v = src[tid];
        uint2 w = make_uint2(pkh(__float2half_rn(v.x), __float2half_rn(v.y)),
                             pkh(__float2half_rn(v.z), __float2half_rn(v.w)));
        __half* dst = (isA ? g_ench : g_uWh) + (size_t)r * 1024;
        ((uint2*)dst)[tid] = w;
    } else {
        int warp = ((b - L - H) << 3) + (tid >> 5);
        int lane = tid & 31;
        const float4* row = (const float4*)(wW + (size_t)warp * H);
        const float4* h4 = (const float4*)h0;
        float s = 0.f;
#pragma unroll
        for (int i = 0; i < 8; i++) {
            float4 a = row[lane + 32 * i];
            float4 hh = h4[lane + 32 * i];
            s += a.x * hh.x + a.y * hh.y + a.z * hh.z + a.w * hh.w;
        }
        s = warp_sum(s);
        if (lane == 0) g_q[warp] = s + wb[warp] + ub[warp];
    }
}

// ---------------- K2: mma.sync fp16 scores GEMM + fused softmax + filler GEMVs ----------------
// blocks [0,256): MMA tiles (bm=(b&31)*128, bn=(b>>5)*128); last finisher does softmax.
// blocks [256,296): co-resident filler: gh = w_hh@hprev + b_hh (3072 rows),
//                   xemb = cW_emb@emb[tok] + cb (1024 rows). Overlaps under tensor-bound MMA.
#define SMEM_DYN (2 * 32768 + 1024)
#define K2_BLOCKS 296

__global__ void __launch_bounds__(256, 2) k2_scores(const float* __restrict__ vW,
                                                    const float* __restrict__ w_hh,
                                                    const float* __restrict__ b_hh,
                                                    const float* __restrict__ cW,
                                                    const float* __restrict__ cb,
                                                    const float* __restrict__ emb,
                                                    const int* __restrict__ tok,
                                                    const float* __restrict__ h0,
                                                    float* __restrict__ out_attn) {
    extern __shared__ char dsm[];
    __shared__ float sq[128], sv[128], sred[128][2];
    __shared__ bool s_last;

    int tid = threadIdx.x, wid = tid >> 5, lane = tid & 31;

    if (blockIdx.x >= 256) {
        // ---- filler: latency-bound GEMVs on LSU/DRAM while MMA blocks own tensor pipe ----
        int wtask = (blockIdx.x - 256) * 8 + wid;      // 0..319
        const float4* h4 = (const float4*)h0;
        const float4* e4 = (const float4*)(emb + (size_t)tok[0] * H);
        for (int idx = wtask; idx < 4096; idx += 320) {
            const float4* row;
            const float4* vec;
            if (idx < 3072) {
                row = (const float4*)(w_hh + (size_t)idx * H);
                vec = h4;
            } else {
                row = (const float4*)(cW + (size_t)(idx - 3072) * 2 * H + H);
                vec = e4;
            }
            float s = 0.f;
#pragma unroll
            for (int i = 0; i < 8; i++) {
                float4 a = row[lane + 32 * i];
                float4 v = vec[lane + 32 * i];
                s += a.x * v.x + a.y * v.y + a.z * v.z + a.w * v.w;
            }
            s = warp_sum(s);
            if (lane == 0) {
                if (idx < 3072) g_gh[idx] = s + b_hh[idx];
                else g_xemb[idx - 3072] = s + cb[idx - 3072];
            }
        }
        return;
    }

    uint32_t sbase = (smem_u32(dsm) + 1023u) & ~1023u;
    int wm = wid & 3, wn = wid >> 2;
    int bm = (blockIdx.x & 31) * 128, bn = (blockIdx.x >> 5) * 128;

    if (tid < 128) { sq[tid] = g_q[bn + tid]; sv[tid] = vW[bn + tid]; }

    const __half* gA = g_ench + (size_t)bm * 1024;
    const __half* gB = g_uWh + (size_t)bn * 1024;

    int lr[4], lc[4];
    uint32_t loff[4];
#pragma unroll
    for (int i = 0; i < 4; i++) {
        int idx = tid + 256 * i;
        lr[i] = idx >> 3;
        lc[i] = idx & 7;
        loff[i] = sw((uint32_t)(lr[i] * 128 + lc[i] * 16));
    }

#define LOAD_CHUNK(c, buf) do { \
    uint32_t o_ = (uint32_t)(c) * 64u; \
    uint32_t s_ = sbase + (buf) * 32768u; \
    _Pragma("unroll") \
    for (int i_ = 0; i_ < 4; i_++) { \
        const __half* a_ = gA + (size_t)lr[i_] * 1024 + o_ + lc[i_] * 8; \
        const __half* b_ = gB + (size_t)lr[i_] * 1024 + o_ + lc[i_] * 8; \
        CP_ASYNC16(s_ + loff[i_], a_); \
        CP_ASYNC16(s_ + 16384u + loff[i_], b_); \
    } \
    CP_COMMIT(); \
} while (0)

    float acc[2][8][4] = {};

    LOAD_CHUNK(0, 0);

    uint32_t aRow[2], bRow[4];
#pragma unroll
    for (int mt = 0; mt < 2; mt++)
        aRow[mt] = (uint32_t)((wm * 32 + mt * 16 + (lane & 15)) * 128 + (lane >> 4) * 16);
#pragma unroll
    for (int bp = 0; bp < 4; bp++)
        bRow[bp] = (uint32_t)((wn * 64 + bp * 16 + (lane & 15)) * 128 + (lane >> 4) * 16);

    for (int c = 0; c < NC; c++) {
        if (c + 1 < NC) {
            LOAD_CHUNK(c + 1, (c + 1) & 1);
            CP_WAIT(1);
        } else {
            CP_WAIT(0);
        }
        __syncthreads();
        uint32_t sA = sbase + (uint32_t)(c & 1) * 32768u;
        uint32_t sB = sA + 16384u;
#pragma unroll
        for (int ks = 0; ks < 4; ks++) {
            uint32_t afr[2][4];
#pragma unroll
            for (int mt = 0; mt < 2; mt++)
                LDSM_X4(afr[mt], sA + sw(aRow[mt] + ks * 32));
            uint32_t bfr[4][4];
#pragma unroll
            for (int bp = 0; bp < 4; bp++)
                LDSM_X4(bfr[bp], sB + sw(bRow[bp] + ks * 32));
#pragma unroll
            for (int mt = 0; mt < 2; mt++)
#pragma unroll
                for (int nt = 0; nt < 8; nt++) {
                    uint32_t b0 = bfr[nt >> 1][nt & 1];
                    uint32_t b1 = bfr[nt >> 1][(nt & 1) + 2];
                    mma_f16(acc[mt][nt], afr[mt], b0, b1);
                }
        }
        __syncthreads();
    }

    // ---- epilogue: weighted tanh row reduction ----
    int cb2 = wn * 64;
    int c0 = 2 * (lane & 3);
    float p[2][2];
#pragma unroll
    for (int mt = 0; mt < 2; mt++)
#pragma unroll
        for (int half = 0; half < 2; half++) {
            float s = 0.f;
#pragma unroll
            for (int nt = 0; nt < 8; nt++) {
#pragma unroll
                for (int j = 0; j < 2; j++) {
                    int n = cb2 + nt * 8 + c0 + j;
                    s += sv[n] * tanhf(sq[n] + acc[mt][nt][half * 2 + j]);
                }
            }
            p[mt][half] = s;
        }
#pragma unroll
    for (int mt = 0; mt < 2; mt++)
#pragma unroll
        for (int half = 0; half < 2; half++) {
            float s = p[mt][half];
            s += __shfl_xor_sync(0xffffffffu, s, 1);
            s += __shfl_xor_sync(0xffffffffu, s, 2);
            p[mt][half] = s;
        }
    if ((lane & 3) == 0) {
#pragma unroll
        for (int mt = 0; mt < 2; mt++)
#pragma unroll
            for (int half = 0; half < 2; half++)
                sred[wm * 32 + mt * 16 + half * 8 + (lane >> 2)][wn] = p[mt][half];
    }
    __syncthreads();
    if (tid < 128)
        atomicAdd(&g_scores[bm + tid], sred[tid][0] + sred[tid][1]);

    // ---- fused softmax in last-finishing MMA block (only MMA blocks count) ----
    __threadfence();
    __syncthreads();
    if (tid == 0) s_last = (atomicAdd(&g_k2cnt, 1u) == 255u);
    __syncthreads();
    if (!s_last) return;
    if (tid == 0) g_k2cnt = 0u;
    float v[16];
    float mx = -1e30f;
#pragma unroll
    for (int i = 0; i < 16; i++) {
        v[i] = g_scores[tid + 256 * i];
        mx = fmaxf(mx, v[i]);
    }
    mx = warp_max(mx);
    if (lane == 0) sq[wid] = mx;
    __syncthreads();
    if (tid < 32) {
        float m2 = (tid < 8) ? sq[tid] : -1e30f;
        m2 = warp_max(m2);
        if (tid == 0) sq[0] = m2;
    }
    __syncthreads();
    mx = sq[0];
    float se = 0.f;
#pragma unroll
    for (int i = 0; i < 16; i++) {
        v[i] = expf(v[i] - mx);
        se += v[i];
    }
    se = warp_sum(se);
    if (lane == 0) sv[wid] = se;
    __syncthreads();
    if (tid < 32) {
        float s2 = (tid < 8) ? sv[tid] : 0.f;
        s2 = warp_sum(s2);
        if (tid == 0) sv[0] = s2;
    }
    __syncthreads();
    float inv = 1.f / sv[0];
#pragma unroll
    for (int i = 0; i < 16; i++) {
        float a = v[i] * inv;
        g_attn[tid + 256 * i] = a;
        out_attn[tid + 256 * i] = a;
    }
}

// ---------------- K_EPI: persistent fused epilogue (context -> combine -> GRU) ----------------
__global__ void __launch_bounds__(1024) k_epi(const float* __restrict__ cW,
                                              const float* __restrict__ w_ih,
                                              const float* __restrict__ b_ih,
                                              const float* __restrict__ hprev,
                                              float* __restrict__ d_out) {
    __shared__ float aw[64];
    __shared__ float2 sbuf[3 * 256];
    __shared__ float s32[32];
    __shared__ unsigned s_gen0;
    int t = threadIdx.x, wid = t >> 5, lane = t & 31;
    int b = blockIdx.x;

    if (t == 0) s_gen0 = g_bar_gen;

    // ---- Phase A: context partials ----
    int bg = b >> 1, ch = b & 1;
    int ci = t & 255;
    int c2 = ch * 256 + ci;
    int rh = t >> 8;
    int l0 = bg * 64 + rh * 16;
    if (t < 64) aw[t] = g_attn[bg * 64 + t];
    __syncthreads();
    unsigned gen0 = s_gen0;
    {
        float s0 = 0.f, s1 = 0.f;
        const float* awh = aw + rh * 16;
#pragma unroll
        for (int bb = 0; bb < 2; bb++) {
            uint32_t e[8];
#pragma unroll
            for (int l = 0; l < 8; l++)
                e[l] = *(const uint32_t*)(g_ench + (size_t)(l0 + bb * 8 + l) * 1024 + 2 * c2);
#pragma unroll
            for (int l = 0; l < 8; l++) {
                float w = awh[bb * 8 + l];
                float2 f = __half22float2(*(__half2*)&e[l]);
                s0 += w * f.x;
                s1 += w * f.y;
            }
        }
        if (rh > 0) sbuf[(rh - 1) * 256 + ci] = make_float2(s0, s1);
        __syncthreads();
        if (rh == 0) {
            float2 a1 = sbuf[ci], a2 = sbuf[256 + ci], a3 = sbuf[512 + ci];
            *(float2*)&g_cpart[bg * H + 2 * c2] =
                make_float2(s0 + a1.x + a2.x + a3.x, s1 + a1.y + a2.y + a3.y);
        }
    }
    grid_sync_128(gen0 + 1);

    // ---- Phase B: distributed context reduce ----
    if (t < 512) {
        int col = b * 8 + (t >> 6);
        int p = t & 63;
        float s = g_cpart[p * H + col];
        s = warp_sum(s);
        if (lane == 0) s32[wid] = s;
    }
    __syncthreads();
    if (t < 8) g_context[b * 8 + t] = s32[2 * t] + s32[2 * t + 1];
    grid_sync_128(gen0 + 2);

    // ---- Phase C: x = relu(cW_ctx@ctx + xemb), 4 warps/row ----
    {
        int task = b * 32 + wid;
        int row = task >> 2, q = task & 3;
        const float4* wr = (const float4*)(cW + (size_t)row * 2 * H + q * 256);
        const float4* vec = (const float4*)(g_context + q * 256);
        float s = 0.f;
#pragma unroll
        for (int i = 0; i < 2; i++) {
            float4 a = wr[lane + 32 * i];
            float4 v = vec[lane + 32 * i];
            s += a.x * v.x + a.y * v.y + a.z * v.z + a.w * v.w;
        }
        s = warp_sum(s);
        if (lane == 0) s32[wid] = s;
        __syncthreads();
        if (t < 8) {
            int row2 = b * 8 + t;
            g_x[row2] = fmaxf(s32[4 * t] + s32[4 * t + 1] + s32[4 * t + 2] + s32[4 * t + 3]
                              + g_xemb[row2], 0.f);
        }
    }
    grid_sync_128(gen0 + 3);

    // ---- Phase D: gi rows grouped per GRU element + block-local GRU/residual ----
    {
        float s = 0.f;
        if (wid < 24) {
            int g = wid >> 3, rr = wid & 7;
            int row = g * H + b * 8 + rr;
            const float4* wr = (const float4*)(w_ih + (size_t)row * H);
            const float4* vec = (const float4*)g_x;
#pragma unroll
            for (int i = 0; i < 8; i++) {
                float4 a = wr[lane + 32 * i];
                float4 v = vec[lane + 32 * i];
                s += a.x * v.x + a.y * v.y + a.z * v.z + a.w * v.w;
            }
            s = warp_sum(s);
            if (lane == 0) s32[wid] = s;
        }
        __syncthreads();
        if (t < 8) {
            int i = b * 8 + t;
            float ir = s32[t] + b_ih[i];
            float iz = s32[8 + t] + b_ih[H + i];
            float inn = s32[16 + t] + b_ih[2 * H + i];
            float r = 1.f / (1.f + expf(-(ir + g_gh[i])));
            float z = 1.f / (1.f + expf(-(iz + g_gh[H + i])));
            float n = tanhf(inn + r * g_gh[2 * H + i]);
            float hp = hprev[i];
            float h = (1.f - z) * n + z * hp;
            d_out[V + i] = h;
            g_ov[i] = g_context[i] + h;
        }
    }
}

// ---------------- K8: logits = outW @ ov + outb (round-12 proven shape) ----------------
__global__ void __launch_bounds__(256) k8_logits(const float* __restrict__ outW,
                                                 const float* __restrict__ outb,
                                                 float* __restrict__ d_out) {
    __shared__ float4 ov[H / 4];
    int t = threadIdx.x;
    ov[t] = ((const float4*)g_ov)[t];
    __syncthreads();
    int warp = t >> 5, lane = t & 31;
    int v = blockIdx.x * 8 + warp;
    const float4* w4 = (const float4*)(outW + (size_t)v * H);
    float s = 0.f;
#pragma unroll
    for (int i = 0; i < 8; i++) {
        float4 a = w4[lane + 32 * i];
        float4 b = ov[lane + 32 * i];
        s += a.x * b.x + a.y * b.y + a.z * b.z + a.w * b.w;
    }
    s = warp_sum(s);
    if (lane == 0) d_out[v] = s + outb[v];
}

// ---------------- launch ----------------
extern "C" void kernel_launch(void* const* d_in, const int* in_sizes, int n_in,
                              void* d_out, int out_size) {
    const int* tok = (const int*)d_in[0];
    const float* hidden = (const float*)d_in[1];
    const float* enc = (const float*)d_in[2];
    const float* emb = (const float*)d_in[3];
    const float* wW = (const float*)d_in[4];
    const float* wb = (const float*)d_in[5];
    const float* uW = (const float*)d_in[6];
    const float* ub = (const float*)d_in[7];
    const float* vW = (const float*)d_in[8];
    const float* cW = (const float*)d_in[9];
    const float* cb = (const float*)d_in[10];
    const float* w_ih = (const float*)d_in[11];
    const float* b_ih = (const float*)d_in[12];
    const float* w_hh = (const float*)d_in[13];
    const float* b_hh = (const float*)d_in[14];
    const float* outW = (const float*)d_in[15];
    const float* outb = (const float*)d_in[16];
    float* out = (float*)d_out;

    cudaFuncSetAttribute(k2_scores, cudaFuncAttributeMaxDynamicSharedMemorySize, SMEM_DYN);

    k_prologue<<<PRO_BLOCKS, 256>>>(enc, uW, hidden, wW, wb, ub);
    k2_scores<<<K2_BLOCKS, 256, SMEM_DYN>>>(vW, w_hh, b_hh, cW, cb, emb, tok, hidden,
                                            out + V + H);
    k_epi<<<128, 1024>>>(cW, w_ih, b_ih, hidden, out);
    k8_logits<<<V / 8, 256>>>(outW, outb, out);
}